// round 1
// baseline (speedup 1.0000x reference)
#include <cuda_runtime.h>
#include <cuda_bf16.h>
#include <cstdint>

// 12-bit ripple-carry adder over float-encoded bits.
// A, B: [BATCH, 12] float32 in {0.0, 1.0}. Bit 11 is LSB.
// Output: sums [BATCH, 12] followed by carry [BATCH, 1] (flattened concat).
//
// Strategy: pack 12 bits -> uint32 (element j -> bit 11-j), single integer
// add, unpack 13 bits. Exact; purely HBM-bound streaming.

__global__ __launch_bounds__(256) void adder12_kernel(
    const float4* __restrict__ A4,
    const float4* __restrict__ B4,
    float4* __restrict__ S4,
    float* __restrict__ Cout,
    int n_rows)
{
    int r = blockIdx.x * blockDim.x + threadIdx.x;
    if (r >= n_rows) return;

    // 12 floats per row = 3 float4 per input
    const float4 a0 = A4[3 * r + 0];
    const float4 a1 = A4[3 * r + 1];
    const float4 a2 = A4[3 * r + 2];
    const float4 b0 = B4[3 * r + 0];
    const float4 b1 = B4[3 * r + 1];
    const float4 b2 = B4[3 * r + 2];

    // Pack: element j (0..11) -> bit (11 - j). Values are exactly 0.0 or 1.0.
    uint32_t av =
        ((uint32_t)a0.x << 11) | ((uint32_t)a0.y << 10) |
        ((uint32_t)a0.z << 10 >> 1) | ((uint32_t)a0.w << 8) |
        ((uint32_t)a1.x << 7)  | ((uint32_t)a1.y << 6) |
        ((uint32_t)a1.z << 5)  | ((uint32_t)a1.w << 4) |
        ((uint32_t)a2.x << 3)  | ((uint32_t)a2.y << 2) |
        ((uint32_t)a2.z << 1)  | ((uint32_t)a2.w << 0);
    uint32_t bv =
        ((uint32_t)b0.x << 11) | ((uint32_t)b0.y << 10) |
        ((uint32_t)b0.z << 9)  | ((uint32_t)b0.w << 8) |
        ((uint32_t)b1.x << 7)  | ((uint32_t)b1.y << 6) |
        ((uint32_t)b1.z << 5)  | ((uint32_t)b1.w << 4) |
        ((uint32_t)b2.x << 3)  | ((uint32_t)b2.y << 2) |
        ((uint32_t)b2.z << 1)  | ((uint32_t)b2.w << 0);

    uint32_t s = av + bv;

    float4 s0, s1, s2;
    s0.x = (float)((s >> 11) & 1u);
    s0.y = (float)((s >> 10) & 1u);
    s0.z = (float)((s >> 9)  & 1u);
    s0.w = (float)((s >> 8)  & 1u);
    s1.x = (float)((s >> 7)  & 1u);
    s1.y = (float)((s >> 6)  & 1u);
    s1.z = (float)((s >> 5)  & 1u);
    s1.w = (float)((s >> 4)  & 1u);
    s2.x = (float)((s >> 3)  & 1u);
    s2.y = (float)((s >> 2)  & 1u);
    s2.z = (float)((s >> 1)  & 1u);
    s2.w = (float)((s >> 0)  & 1u);

    S4[3 * r + 0] = s0;
    S4[3 * r + 1] = s1;
    S4[3 * r + 2] = s2;
    Cout[r] = (float)((s >> 12) & 1u);
}

extern "C" void kernel_launch(void* const* d_in, const int* in_sizes, int n_in,
                              void* d_out, int out_size)
{
    const float* A = (const float*)d_in[0];
    const float* B = (const float*)d_in[1];
    float* out = (float*)d_out;

    const int n_rows = in_sizes[0] / 12;  // 4194304

    float4* S4 = (float4*)out;            // sums block: n_rows * 12 floats
    float* Cout = out + (size_t)n_rows * 12;  // carry block: n_rows floats

    const int threads = 256;
    const int blocks = (n_rows + threads - 1) / threads;
    adder12_kernel<<<blocks, threads>>>(
        (const float4*)A, (const float4*)B, S4, Cout, n_rows);
}